// round 3
// baseline (speedup 1.0000x reference)
#include <cuda_runtime.h>
#include <cstdint>

#define TPB 128
#define NSTATE 4

// ---------- f32x2 packed-math helpers (Blackwell packed-FFMA path) ----------
static __device__ __forceinline__ unsigned long long pack2(float lo, float hi) {
    unsigned long long r;
    asm("mov.b64 %0, {%1, %2};" : "=l"(r) : "f"(lo), "f"(hi));
    return r;
}
static __device__ __forceinline__ void unpack2(unsigned long long v, float& lo, float& hi) {
    asm("mov.b64 {%0, %1}, %2;" : "=f"(lo), "=f"(hi) : "l"(v));
}
static __device__ __forceinline__ unsigned long long mul2(unsigned long long a, unsigned long long b) {
    unsigned long long r;
    asm("mul.rn.f32x2 %0, %1, %2;" : "=l"(r) : "l"(a), "l"(b));
    return r;
}
static __device__ __forceinline__ unsigned long long fma2(unsigned long long a, unsigned long long b, unsigned long long c) {
    unsigned long long r;
    asm("fma.rn.f32x2 %0, %1, %2, %3;" : "=l"(r) : "l"(a), "l"(b), "l"(c));
    return r;
}
static __device__ __forceinline__ unsigned long long add2(unsigned long long a, unsigned long long b) {
    unsigned long long r;
    asm("add.rn.f32x2 %0, %1, %2;" : "=l"(r) : "l"(a), "l"(b));
    return r;
}

// ---------- float-only mod-2pi reduction (split constant) ----------
#define INV2PI_F   0.15915494f
#define TWOPI_HI_F 6.28318548202514648f   /* nearest float to 2*pi */
#define TWOPI_LO_F (-1.7484555e-07f)      /* 2*pi - TWOPI_HI (double) */

// Reduce x mod 2*pi into ~[-pi, pi], all float.  The split constant keeps
// the reduction itself accurate to ~1e-6 rad even for |x| up to ~300.
static __device__ __forceinline__ float reduce_2pi(float x) {
    float k = rintf(x * INV2PI_F);
    float r = fmaf(-k, TWOPI_HI_F, x);
    r = fmaf(-k, TWOPI_LO_F, r);
    return r;
}

// ---------- per-block (per-h) constants, ALL FLOAT ----------
struct BlockConsts {
    float adr[NSTATE];      // Re(A*dt)  (f32-rounded like the reference)
    float adi[NSTATE];      // Im(A*dt)  (f32-rounded like the reference)
    float coef_re[NSTATE];  // C * B_bar
    float coef_im[NSTATE];
    float w_re[NSTATE];     // w = exp(Adt * TPB)
    float w_im[NSTATE];
    float rec_a[NSTATE];    // 2*Re(w)
    float rec_b[NSTATE];    // -|w|^2 = -exp(2*adr*TPB)
};

static __device__ __forceinline__ void setup_consts(
    BlockConsts* bc,
    const float* __restrict__ log_dt,
    const float* __restrict__ log_A_real,
    const float* __restrict__ A_imag,
    const float* __restrict__ VinvB_re,
    const float* __restrict__ VinvB_im,
    const float* __restrict__ CV_re,
    const float* __restrict__ CV_im,
    int h)
{
    if (threadIdx.x < NSTATE) {
        int n = threadIdx.x;
        int idx = h * NSTATE + n;
        float dt  = __expf(log_dt[h]);
        float Are = -__expf(log_A_real[idx]);
        float Aim = A_imag[idx];
        float adr = Are * dt;
        float adi = Aim * dt;

        // A_bar = exp(Adt)
        float e = __expf(adr);
        float sb, cb;
        __sincosf(adi, &sb, &cb);
        float abr = e * cb, abi = e * sb;

        // B_bar = (A_bar - 1) * B / A
        float br = VinvB_re[idx], bi = VinvB_im[idx];
        float nr = (abr - 1.0f) * br - abi * bi;
        float ni = (abr - 1.0f) * bi + abi * br;
        float den = 1.0f / (Are * Are + Aim * Aim);
        float bbr = (nr * Are + ni * Aim) * den;
        float bbi = (ni * Are - nr * Aim) * den;

        // coef = C * B_bar
        float cr = CV_re[idx], ci = CV_im[idx];
        float cfr = cr * bbr - ci * bbi;
        float cfi = cr * bbi + ci * bbr;

        // w = exp(Adt * TPB).  adi*TPB is EXACT in float (TPB = 2^7).
        float wm = __expf(adr * (float)TPB);
        float ph = reduce_2pi(adi * (float)TPB);
        float ws, wc;
        __sincosf(ph, &ws, &wc);
        float wr = wm * wc, wi = wm * ws;

        bc->adr[n] = adr;
        bc->adi[n] = adi;
        bc->coef_re[n] = cfr;
        bc->coef_im[n] = cfi;
        bc->w_re[n] = wr;
        bc->w_im[n] = wi;
        bc->rec_a[n] = 2.0f * wr;
        bc->rec_b[n] = -(wm * wm);
    }
    __syncthreads();
}

// Per-thread seeds:
//   x0[n] = Re(coef_n * exp(Adt_n * t))
//   x1[n] = Re(coef_n * exp(Adt_n * (t + TPB)))
// Phase is f32round(adi * t) — the SAME single rounding the complex64
// reference applies before its range reduction (bug-compatible).
static __device__ __forceinline__ void seed_states(
    const BlockConsts* bc, int t, float* x0, float* x1)
{
    float tf = (float)t;
#pragma unroll
    for (int n = 0; n < NSTATE; n++) {
        float ang = reduce_2pi(tf * bc->adi[n]);
        float m = __expf(bc->adr[n] * tf);
        float s, c;
        __sincosf(ang, &s, &c);
        float sre = m * c, sim = m * s;
        float cr = bc->coef_re[n] * sre - bc->coef_im[n] * sim; // Re(coef * z^t)
        float ci = bc->coef_re[n] * sim + bc->coef_im[n] * sre; // Im(coef * z^t)
        x0[n] = cr;
        x1[n] = cr * bc->w_re[n] - ci * bc->w_im[n];            // Re(coef * z^t * w)
    }
}

// Order-2 real recurrence per state:  x_{k+2} = 2Re(w)·x_{k+1} - |w|²·x_k.
// Exact for x_k = Re(z0 · w^k); unconditionally stable since |w| < 1.
template <int ITERS>
__global__ void __launch_bounds__(TPB, 8)
ssm_vandermonde_kernel(
    const float* __restrict__ log_dt,
    const float* __restrict__ log_A_real,
    const float* __restrict__ A_imag,
    const float* __restrict__ VinvB_re,
    const float* __restrict__ VinvB_im,
    const float* __restrict__ CV_re,
    const float* __restrict__ CV_im,
    float* __restrict__ out,
    int L)
{
    __shared__ BlockConsts bc;
    int h = blockIdx.x;
    setup_consts(&bc, log_dt, log_A_real, A_imag, VinvB_re, VinvB_im, CV_re, CV_im, h);

    int t = threadIdx.x;
    float x0[NSTATE], x1[NSTATE];
    seed_states(&bc, t, x0, x1);

    // Pack state pairs (n0,n1) and (n2,n3) into f32x2 registers.
    unsigned long long X0a = pack2(x0[0], x0[1]), X0b = pack2(x0[2], x0[3]);
    unsigned long long X1a = pack2(x1[0], x1[1]), X1b = pack2(x1[2], x1[3]);
    unsigned long long Aa = pack2(bc.rec_a[0], bc.rec_a[1]), Ab = pack2(bc.rec_a[2], bc.rec_a[3]);
    unsigned long long Ba = pack2(bc.rec_b[0], bc.rec_b[1]), Bb = pack2(bc.rec_b[2], bc.rec_b[3]);

    float* op = out + (size_t)h * (size_t)L + t;

#pragma unroll
    for (int k = 0; k < ITERS; k += 2) {
        // output k from X0
        {
            unsigned long long s2 = add2(X0a, X0b);
            float lo, hi;
            unpack2(s2, lo, hi);
            op[k * TPB] = lo + hi;
        }
        // x_{k+2} = a*x_{k+1} + b*x_k
        unsigned long long Ta = fma2(Aa, X1a, mul2(Ba, X0a));
        unsigned long long Tb = fma2(Ab, X1b, mul2(Bb, X0b));
        // output k+1 from X1
        {
            unsigned long long s2 = add2(X1a, X1b);
            float lo, hi;
            unpack2(s2, lo, hi);
            op[(k + 1) * TPB] = lo + hi;
        }
        // x_{k+3} = a*x_{k+2} + b*x_{k+1}
        unsigned long long T2a = fma2(Aa, Ta, mul2(Ba, X1a));
        unsigned long long T2b = fma2(Ab, Tb, mul2(Bb, X1b));
        X0a = Ta;  X0b = Tb;
        X1a = T2a; X1b = T2b;
    }
}

// Generic fallback (any L), float only.
__global__ void __launch_bounds__(TPB, 8)
ssm_vandermonde_generic(
    const float* __restrict__ log_dt,
    const float* __restrict__ log_A_real,
    const float* __restrict__ A_imag,
    const float* __restrict__ VinvB_re,
    const float* __restrict__ VinvB_im,
    const float* __restrict__ CV_re,
    const float* __restrict__ CV_im,
    float* __restrict__ out,
    int L)
{
    __shared__ BlockConsts bc;
    int h = blockIdx.x;
    setup_consts(&bc, log_dt, log_A_real, A_imag, VinvB_re, VinvB_im, CV_re, CV_im, h);

    int t = threadIdx.x;
    float x0[NSTATE], x1[NSTATE];
    seed_states(&bc, t, x0, x1);

    float a[NSTATE], b[NSTATE];
#pragma unroll
    for (int n = 0; n < NSTATE; n++) { a[n] = bc.rec_a[n]; b[n] = bc.rec_b[n]; }

    float* op = out + (size_t)h * (size_t)L;
    for (int l = t; l < L; l += TPB) {
        float s = (x0[0] + x0[1]) + (x0[2] + x0[3]);
        op[l] = s;
#pragma unroll
        for (int n = 0; n < NSTATE; n++) {
            float nx = fmaf(a[n], x1[n], b[n] * x0[n]);
            x0[n] = x1[n];
            x1[n] = nx;
        }
    }
}

extern "C" void kernel_launch(void* const* d_in, const int* in_sizes, int n_in,
                              void* d_out, int out_size)
{
    const float* log_dt     = (const float*)d_in[0];
    const float* log_A_real = (const float*)d_in[1];
    const float* A_imag     = (const float*)d_in[2];
    const float* VinvB_re   = (const float*)d_in[3];
    const float* VinvB_im   = (const float*)d_in[4];
    const float* CV_re      = (const float*)d_in[5];
    const float* CV_im      = (const float*)d_in[6];
    float* out = (float*)d_out;

    int H = in_sizes[0];           // log_dt has H elements
    int L = out_size / H;          // output is (H, L)

    if (L == 32 * TPB) {
        ssm_vandermonde_kernel<32><<<H, TPB>>>(
            log_dt, log_A_real, A_imag, VinvB_re, VinvB_im, CV_re, CV_im, out, L);
    } else if (L == 16 * TPB) {
        ssm_vandermonde_kernel<16><<<H, TPB>>>(
            log_dt, log_A_real, A_imag, VinvB_re, VinvB_im, CV_re, CV_im, out, L);
    } else if (L == 64 * TPB) {
        ssm_vandermonde_kernel<64><<<H, TPB>>>(
            log_dt, log_A_real, A_imag, VinvB_re, VinvB_im, CV_re, CV_im, out, L);
    } else if (L == 8 * TPB) {
        ssm_vandermonde_kernel<8><<<H, TPB>>>(
            log_dt, log_A_real, A_imag, VinvB_re, VinvB_im, CV_re, CV_im, out, L);
    } else {
        ssm_vandermonde_generic<<<H, TPB>>>(
            log_dt, log_A_real, A_imag, VinvB_re, VinvB_im, CV_re, CV_im, out, L);
    }
}

// round 5
// speedup vs baseline: 1.0269x; 1.0269x over previous
#include <cuda_runtime.h>
#include <cstdint>

#define NSTATE 4

// ---------- f32x2 packed-math helpers (Blackwell packed-FFMA path) ----------
static __device__ __forceinline__ unsigned long long pack2(float lo, float hi) {
    unsigned long long r;
    asm("mov.b64 %0, {%1, %2};" : "=l"(r) : "f"(lo), "f"(hi));
    return r;
}
static __device__ __forceinline__ void unpack2(unsigned long long v, float& lo, float& hi) {
    asm("mov.b64 {%0, %1}, %2;" : "=f"(lo), "=f"(hi) : "l"(v));
}
static __device__ __forceinline__ unsigned long long mul2(unsigned long long a, unsigned long long b) {
    unsigned long long r;
    asm("mul.rn.f32x2 %0, %1, %2;" : "=l"(r) : "l"(a), "l"(b));
    return r;
}
static __device__ __forceinline__ unsigned long long fma2(unsigned long long a, unsigned long long b, unsigned long long c) {
    unsigned long long r;
    asm("fma.rn.f32x2 %0, %1, %2, %3;" : "=l"(r) : "l"(a), "l"(b), "l"(c));
    return r;
}
static __device__ __forceinline__ unsigned long long add2(unsigned long long a, unsigned long long b) {
    unsigned long long r;
    asm("add.rn.f32x2 %0, %1, %2;" : "=l"(r) : "l"(a), "l"(b));
    return r;
}

// ---------- float-only mod-2pi reduction (split constant) ----------
#define INV2PI_F   0.15915494f
#define TWOPI_HI_F 6.28318548202514648f   /* nearest float to 2*pi */
#define TWOPI_LO_F (-1.7484555e-07f)      /* 2*pi - TWOPI_HI (double) */

static __device__ __forceinline__ float reduce_2pi(float x) {
    float k = rintf(x * INV2PI_F);
    float r = fmaf(-k, TWOPI_HI_F, x);
    r = fmaf(-k, TWOPI_LO_F, r);
    return r;
}

// ---------- per-block (per-h) constants, ALL FLOAT ----------
struct BlockConsts {
    float adr[NSTATE];      // Re(A*dt)
    float adi[NSTATE];      // Im(A*dt)
    float coef_re[NSTATE];  // C * B_bar
    float coef_im[NSTATE];
    float w_re[NSTATE];     // w = exp(Adt * STRIDE)
    float w_im[NSTATE];
    float rec_a[NSTATE];    // 2*Re(w)
    float rec_b[NSTATE];    // -|w|^2
};

template <int STRIDE>
static __device__ __forceinline__ void setup_consts(
    BlockConsts* bc,
    const float* __restrict__ log_dt,
    const float* __restrict__ log_A_real,
    const float* __restrict__ A_imag,
    const float* __restrict__ VinvB_re,
    const float* __restrict__ VinvB_im,
    const float* __restrict__ CV_re,
    const float* __restrict__ CV_im,
    int h)
{
    if (threadIdx.x < NSTATE) {
        int n = threadIdx.x;
        int idx = h * NSTATE + n;
        float dt  = __expf(log_dt[h]);
        float Are = -__expf(log_A_real[idx]);
        float Aim = A_imag[idx];
        float adr = Are * dt;
        float adi = Aim * dt;

        // A_bar = exp(Adt)
        float e = __expf(adr);
        float sb, cb;
        __sincosf(adi, &sb, &cb);
        float abr = e * cb, abi = e * sb;

        // B_bar = (A_bar - 1) * B / A
        float br = VinvB_re[idx], bi = VinvB_im[idx];
        float nr = (abr - 1.0f) * br - abi * bi;
        float ni = (abr - 1.0f) * bi + abi * br;
        float den = 1.0f / (Are * Are + Aim * Aim);
        float bbr = (nr * Are + ni * Aim) * den;
        float bbi = (ni * Are - nr * Aim) * den;

        // coef = C * B_bar
        float cr = CV_re[idx], ci = CV_im[idx];
        float cfr = cr * bbr - ci * bbi;
        float cfi = cr * bbi + ci * bbr;

        // w = exp(Adt * STRIDE). adi*STRIDE is EXACT in float (STRIDE = 2^k).
        float wm = __expf(adr * (float)STRIDE);
        float ph = reduce_2pi(adi * (float)STRIDE);
        float ws, wc;
        __sincosf(ph, &ws, &wc);
        float wr = wm * wc;

        bc->adr[n] = adr;
        bc->adi[n] = adi;
        bc->coef_re[n] = cfr;
        bc->coef_im[n] = cfi;
        bc->w_re[n] = wr;
        bc->w_im[n] = wm * ws;
        bc->rec_a[n] = 2.0f * wr;
        bc->rec_b[n] = -(wm * wm);
    }
    __syncthreads();
}

// Per-thread seeds:
//   x0[n] = Re(coef_n * exp(Adt_n * t))
//   x1[n] = Re(coef_n * exp(Adt_n * (t + STRIDE)))
static __device__ __forceinline__ void seed_states(
    const BlockConsts* bc, int t, float* x0, float* x1)
{
    float tf = (float)t;
#pragma unroll
    for (int n = 0; n < NSTATE; n++) {
        float ang = reduce_2pi(tf * bc->adi[n]);
        float m = __expf(bc->adr[n] * tf);
        float s, c;
        __sincosf(ang, &s, &c);
        float sre = m * c, sim = m * s;
        float cr = bc->coef_re[n] * sre - bc->coef_im[n] * sim; // Re(coef * z^t)
        float ci = bc->coef_re[n] * sim + bc->coef_im[n] * sre; // Im(coef * z^t)
        x0[n] = cr;
        x1[n] = cr * bc->w_re[n] - ci * bc->w_im[n];            // Re(coef * z^t * w)
    }
}

// Order-2 real recurrence per state: x_{k+2} = 2Re(w)·x_{k+1} - |w|²·x_k.
// Exact for x_k = Re(z0·w^k); unconditionally stable since |w| < 1.
// TPB=64 + 16 blocks/SM -> 2048 blocks fit in ONE wave on 148 SMs (cap 2368).
template <int TPB, int ITERS>
__global__ void __launch_bounds__(TPB, 16)
ssm_vandermonde_kernel(
    const float* __restrict__ log_dt,
    const float* __restrict__ log_A_real,
    const float* __restrict__ A_imag,
    const float* __restrict__ VinvB_re,
    const float* __restrict__ VinvB_im,
    const float* __restrict__ CV_re,
    const float* __restrict__ CV_im,
    float* __restrict__ out,
    int L)
{
    __shared__ BlockConsts bc;
    int h = blockIdx.x;
    setup_consts<TPB>(&bc, log_dt, log_A_real, A_imag, VinvB_re, VinvB_im, CV_re, CV_im, h);

    int t = threadIdx.x;
    float x0[NSTATE], x1[NSTATE];
    seed_states(&bc, t, x0, x1);

    // Pack state pairs (n0,n1) and (n2,n3) into f32x2 registers.
    unsigned long long X0a = pack2(x0[0], x0[1]), X0b = pack2(x0[2], x0[3]);
    unsigned long long X1a = pack2(x1[0], x1[1]), X1b = pack2(x1[2], x1[3]);
    unsigned long long Aa = pack2(bc.rec_a[0], bc.rec_a[1]), Ab = pack2(bc.rec_a[2], bc.rec_a[3]);
    unsigned long long Ba = pack2(bc.rec_b[0], bc.rec_b[1]), Bb = pack2(bc.rec_b[2], bc.rec_b[3]);

    float* op = out + (size_t)h * (size_t)L + t;

#pragma unroll
    for (int k = 0; k < ITERS; k += 2) {
        // output k from X0
        {
            unsigned long long s2 = add2(X0a, X0b);
            float lo, hi;
            unpack2(s2, lo, hi);
            op[k * TPB] = lo + hi;
        }
        // x_{k+2} = a*x_{k+1} + b*x_k
        unsigned long long Ta = fma2(Aa, X1a, mul2(Ba, X0a));
        unsigned long long Tb = fma2(Ab, X1b, mul2(Bb, X0b));
        // output k+1 from X1
        {
            unsigned long long s2 = add2(X1a, X1b);
            float lo, hi;
            unpack2(s2, lo, hi);
            op[(k + 1) * TPB] = lo + hi;
        }
        // x_{k+3} = a*x_{k+2} + b*x_{k+1}
        unsigned long long T2a = fma2(Aa, Ta, mul2(Ba, X1a));
        unsigned long long T2b = fma2(Ab, Tb, mul2(Bb, X1b));
        X0a = Ta;  X0b = Tb;
        X1a = T2a; X1b = T2b;
    }
}

// Generic fallback (any L), float only.
__global__ void __launch_bounds__(64, 16)
ssm_vandermonde_generic(
    const float* __restrict__ log_dt,
    const float* __restrict__ log_A_real,
    const float* __restrict__ A_imag,
    const float* __restrict__ VinvB_re,
    const float* __restrict__ VinvB_im,
    const float* __restrict__ CV_re,
    const float* __restrict__ CV_im,
    float* __restrict__ out,
    int L)
{
    __shared__ BlockConsts bc;
    int h = blockIdx.x;
    setup_consts<64>(&bc, log_dt, log_A_real, A_imag, VinvB_re, VinvB_im, CV_re, CV_im, h);

    int t = threadIdx.x;
    float x0[NSTATE], x1[NSTATE];
    seed_states(&bc, t, x0, x1);

    float a[NSTATE], b[NSTATE];
#pragma unroll
    for (int n = 0; n < NSTATE; n++) { a[n] = bc.rec_a[n]; b[n] = bc.rec_b[n]; }

    float* op = out + (size_t)h * (size_t)L;
    for (int l = t; l < L; l += 64) {
        float s = (x0[0] + x0[1]) + (x0[2] + x0[3]);
        op[l] = s;
#pragma unroll
        for (int n = 0; n < NSTATE; n++) {
            float nx = fmaf(a[n], x1[n], b[n] * x0[n]);
            x0[n] = x1[n];
            x1[n] = nx;
        }
    }
}

extern "C" void kernel_launch(void* const* d_in, const int* in_sizes, int n_in,
                              void* d_out, int out_size)
{
    const float* log_dt     = (const float*)d_in[0];
    const float* log_A_real = (const float*)d_in[1];
    const float* A_imag     = (const float*)d_in[2];
    const float* VinvB_re   = (const float*)d_in[3];
    const float* VinvB_im   = (const float*)d_in[4];
    const float* CV_re      = (const float*)d_in[5];
    const float* CV_im      = (const float*)d_in[6];
    float* out = (float*)d_out;

    int H = in_sizes[0];           // log_dt has H elements
    int L = out_size / H;          // output is (H, L)

    if (L == 4096) {
        ssm_vandermonde_kernel<64, 64><<<H, 64>>>(
            log_dt, log_A_real, A_imag, VinvB_re, VinvB_im, CV_re, CV_im, out, L);
    } else if (L == 2048) {
        ssm_vandermonde_kernel<64, 32><<<H, 64>>>(
            log_dt, log_A_real, A_imag, VinvB_re, VinvB_im, CV_re, CV_im, out, L);
    } else if (L == 8192) {
        ssm_vandermonde_kernel<64, 128><<<H, 64>>>(
            log_dt, log_A_real, A_imag, VinvB_re, VinvB_im, CV_re, CV_im, out, L);
    } else if (L == 1024) {
        ssm_vandermonde_kernel<64, 16><<<H, 64>>>(
            log_dt, log_A_real, A_imag, VinvB_re, VinvB_im, CV_re, CV_im, out, L);
    } else {
        ssm_vandermonde_generic<<<H, 64>>>(
            log_dt, log_A_real, A_imag, VinvB_re, VinvB_im, CV_re, CV_im, out, L);
    }
}